// round 14
// baseline (speedup 1.0000x reference)
#include <cuda_runtime.h>
#include <cuda_bf16.h>
#include <stdint.h>

// Rejection sampler for speculative decoding — FUSED single kernel.
// SLICES=8, 64-thread blocks (single-wave residency), MLP-16 float4 streaming.
// Output float32 [B*(K+1) + 4*B]:
//  out[B,K+1], num_accepted[B], accepted_counts[B], recovered_counts[B], bonus_counts[B]

#define NT      64
#define NW      (NT / 32)
#define MAXB    512      // max sequences
#define CHUNK   512      // elements per chunk
#define MAXC    256      // max chunks (V <= ~131072)
#define SLICES  8        // streaming blocks per sequence

// ---- device scratch (allocation-free; g_count zero-init, reset by last block) ----
__device__ int   g_count[MAXB];
__device__ float g_chunkA[MAXB * MAXC];
__device__ float g_chunkT[MAXB * MAXC];

__global__ __launch_bounds__(NT) void fused_kernel(
    const int* __restrict__ dtoks,
    const int* __restrict__ ndraft,
    const float* __restrict__ dp,
    const float* __restrict__ tp,
    const int* __restrict__ bonus,
    const float* __restrict__ us,
    const float* __restrict__ ru,
    float* __restrict__ out,
    int B, int K, long long V)
{
    const int b = blockIdx.x / SLICES;
    const int s = blockIdx.x % SLICES;
    const int t = threadIdx.x;
    const int w = t >> 5;
    const int lane = t & 31;

    __shared__ int sh_red[NW];
    __shared__ int sh_start;
    __shared__ int sh_numacc;
    __shared__ int sh_allacc;
    __shared__ int sh_dtok[32];
    __shared__ int sh_last;

    // ---- starts[b] = sum ndraft[0..b-1]; each thread covers t, t+NT, ... ----
    {
        int v = 0;
        for (int i = t; i < b; i += NT) v += ndraft[i];
        #pragma unroll
        for (int off = 16; off; off >>= 1)
            v += __shfl_down_sync(0xffffffffu, v, off);
        if (lane == 0) sh_red[w] = v;
        __syncthreads();
        if (t == 0) {
            int sum = 0;
            #pragma unroll
            for (int i = 0; i < NW; i++) sum += sh_red[i];
            sh_start = sum;
        }
        __syncthreads();
    }
    const int start = sh_start;
    const int nb = ndraft[b];

    // ---- accept phase (warp 0; redundant per slice -> L2 hits after first) ----
    if (t < 32) {
        int k = lane;
        int acc = 0;
        if (k < nb) {
            int idx = start + k;
            int tok = dtoks[idx];
            float pd = fmaxf(dp[(size_t)idx * V + tok], 1e-10f);
            float pt = tp[(size_t)idx * V + tok];
            float ap = fminf(1.0f, pt / pd);
            acc = (us[idx] < ap) ? 1 : 0;
            sh_dtok[k] = tok;
        }
        unsigned m = __ballot_sync(0xffffffffu, (k >= nb) || !acc);
        int numacc = __ffs(m) - 1;
        if (lane == 0) {
            sh_numacc = numacc;
            sh_allacc = (numacc == nb) ? 1 : 0;
        }
    }
    __syncthreads();
    const int numacc = sh_numacc;
    const bool allacc = (sh_allacc != 0);

    // ---- light outputs (slice 0 only) ----
    if (s == 0) {
        if (t <= K) {
            bool is_final = (t == numacc);
            float v;
            if (t < numacc)      v = (float)sh_dtok[t];
            else if (is_final)   v = (float)bonus[b];   // valid only if allacc
            else                 v = -1.0f;
            if (!(is_final && !allacc))
                out[b * (K + 1) + t] = v;
        }
        if (t == 0) {
            int base = B * (K + 1);
            out[base + b]         = (float)(numacc + 1);
            out[base + B + b]     = (float)numacc;
            out[base + 2 * B + b] = allacc ? 0.0f : 1.0f;
            out[base + 3 * B + b] = allacc ? 1.0f : 0.0f;
        }
    }
    if (allacc) return;   // counter untouched: stays 0 for next replay

    // ---- streaming setup: 16B-aligned virtual origin ----
    const int row = start + numacc;
    const long long rowoff = (long long)row * V;
    const int roff = (int)(rowoff & 3);             // elems past 16B boundary
    const float* __restrict__ tA = tp + (rowoff - roff);   // 16B aligned
    const float* __restrict__ dA = dp + (rowoff - roff);
    const long long VL = V + roff;                  // virtual length
    const int nchunks = (int)((VL + CHUNK - 1) / CHUNK);
    const int cps = (nchunks + SLICES - 1) / SLICES;
    const int c0 = s * cps;
    const int c1 = min(c0 + cps, nchunks);

    for (int c = c0 + w; c < c1; c += NW) {
        float sa = 0.f, st = 0.f;
        if (c == 0 || c == nchunks - 1) {
            // scalar masked path (lead phantoms / row tail)
            long long vb = (long long)c * CHUNK + lane * 16;
            #pragma unroll
            for (int l = 0; l < 16; l++) {
                long long vj = vb + l;
                if (vj >= roff && vj < VL) {
                    float tv = __ldcs(tA + vj);
                    float dv = __ldcs(dA + vj);
                    st += tv;
                    sa += fmaxf(tv - dv, 0.f);
                }
            }
        } else {
            // vector path: 16 independent LDG.128 all in flight (MLP-16)
            const float4* __restrict__ t4 = (const float4*)tA + (long long)c * (CHUNK / 4);
            const float4* __restrict__ d4 = (const float4*)dA + (long long)c * (CHUNK / 4);
            float4 av[4], bv[4];
            #pragma unroll
            for (int l = 0; l < 4; l++) av[l] = __ldcs(t4 + l * 32 + lane);
            #pragma unroll
            for (int l = 0; l < 4; l++) bv[l] = __ldcs(d4 + l * 32 + lane);
            #pragma unroll
            for (int l = 0; l < 4; l++) {
                st += ((av[l].x + av[l].y) + (av[l].z + av[l].w));
                sa += ((fmaxf(av[l].x - bv[l].x, 0.f) + fmaxf(av[l].y - bv[l].y, 0.f))
                    +  (fmaxf(av[l].z - bv[l].z, 0.f) + fmaxf(av[l].w - bv[l].w, 0.f)));
            }
        }
        #pragma unroll
        for (int off = 16; off; off >>= 1) {
            sa += __shfl_down_sync(0xffffffffu, sa, off);
            st += __shfl_down_sync(0xffffffffu, st, off);
        }
        if (lane == 0) {
            g_chunkA[b * MAXC + c] = sa;
            g_chunkT[b * MAXC + c] = st;
        }
    }

    // ---- last-block-does-selection handshake ----
    __threadfence();
    __syncthreads();
    if (t == 0) {
        int prev = atomicAdd(&g_count[b], 1);
        int last = (prev == SLICES - 1);
        if (last) atomicExch(&g_count[b], 0);   // replay-safe reset
        sh_last = last;
    }
    __syncthreads();
    if (!sh_last) return;
    __threadfence();

    // ---- selection: monotone scan over chunk sums, then in-chunk refine ----
    __shared__ float sA[MAXC];
    __shared__ float sT[MAXC];
    __shared__ float sh_thr, sh_coff;
    __shared__ int   sh_cstar, sh_modeT;

    for (int i = t; i < nchunks; i += NT) {
        sA[i] = g_chunkA[b * MAXC + i];
        sT[i] = g_chunkT[b * MAXC + i];
    }
    __syncthreads();

    if (t == 0) {
        float sTot = 0.f;
        for (int c = 0; c < nchunks; c++) sTot += sA[c];
        int modeT = !(sTot > 1e-10f);
        float u = ru[b];
        float thr = modeT ? u : u * sTot;
        const float* cs = modeT ? sT : sA;
        float pref = 0.f, coff = 0.f;
        int cstar = nchunks;
        for (int c = 0; c < nchunks; c++) {
            float np = pref + cs[c];
            if (np >= thr) { cstar = c; coff = pref; break; }
            pref = np;
        }
        sh_thr = thr; sh_coff = coff; sh_cstar = cstar; sh_modeT = modeT;
    }
    __syncthreads();

    if (t < 32) {
        int cstar = sh_cstar;
        int recovered;
        if (cstar >= nchunks) {
            recovered = (int)V - 1;
        } else {
            float thr = sh_thr;
            float off = sh_coff;
            bool modeT = (sh_modeT != 0);
            long long vbase = (long long)cstar * CHUNK;
            float vals[16];
            float lsum = 0.f;
            #pragma unroll
            for (int l = 0; l < 16; l++) {
                long long vj = vbase + lane * 16 + l;
                float a = 0.f;
                if (vj >= roff && vj < VL) {
                    float tv = tA[vj];
                    a = modeT ? tv : fmaxf(tv - dA[vj], 0.f);
                }
                vals[l] = a;
                lsum += a;
            }
            float incv = lsum;
            #pragma unroll
            for (int d = 1; d < 32; d <<= 1) {
                float y = __shfl_up_sync(0xffffffffu, incv, d);
                if (lane >= d) incv += y;
            }
            float p = off + (incv - lsum);
            int cnt = 0;
            #pragma unroll
            for (int l = 0; l < 16; l++) {
                p += vals[l];
                long long vj = vbase + lane * 16 + l;
                if (p < thr && vj >= roff && vj < VL) cnt++;
            }
            #pragma unroll
            for (int o = 16; o; o >>= 1)
                cnt += __shfl_down_sync(0xffffffffu, cnt, o);
            int before = (int)vbase - roff;
            if (before < 0) before = 0;
            recovered = before + cnt;
            if (recovered > (int)V - 1) recovered = (int)V - 1;
        }
        if (lane == 0)
            out[b * (K + 1) + numacc] = (float)recovered;
    }
}

extern "C" void kernel_launch(void* const* d_in, const int* in_sizes, int n_in,
                              void* d_out, int out_size)
{
    const int*   dtoks  = (const int*)  d_in[0];
    const int*   ndraft = (const int*)  d_in[1];
    const float* dp     = (const float*)d_in[2];
    const float* tp     = (const float*)d_in[3];
    const int*   bonus  = (const int*)  d_in[4];
    const float* us     = (const float*)d_in[5];
    const float* ru     = (const float*)d_in[6];

    int T = in_sizes[0];
    int B = in_sizes[1];
    long long V = (long long)in_sizes[2] / T;
    int K = out_size / B - 5;   // out layout: B*(K+1) + 4*B

    fused_kernel<<<B * SLICES, NT>>>(dtoks, ndraft, dp, tp, bonus, us, ru,
                                     (float*)d_out, B, K, V);
}

// round 17
// speedup vs baseline: 1.0949x; 1.0949x over previous
#include <cuda_runtime.h>
#include <cuda_bf16.h>
#include <stdint.h>

// Rejection sampler for speculative decoding — FUSED single kernel.
// R11 config (NT=128, SLICES=8, minblocks 10) with L2-friendly default loads:
// the timed graph replays reuse the same ~61MB of rejected rows, which fit L2.
// Output float32 [B*(K+1) + 4*B]:
//  out[B,K+1], num_accepted[B], accepted_counts[B], recovered_counts[B], bonus_counts[B]

#define NT      128
#define NW      (NT / 32)
#define MAXB    512      // max sequences
#define CHUNK   512      // elements per chunk
#define MAXC    256      // max chunks (V <= ~131072)
#define SLICES  8        // streaming blocks per sequence

// ---- device scratch (allocation-free; g_count zero-init, reset by last block) ----
__device__ int   g_count[MAXB];
__device__ float g_chunkA[MAXB * MAXC];
__device__ float g_chunkT[MAXB * MAXC];

__global__ __launch_bounds__(NT, 10) void fused_kernel(
    const int* __restrict__ dtoks,
    const int* __restrict__ ndraft,
    const float* __restrict__ dp,
    const float* __restrict__ tp,
    const int* __restrict__ bonus,
    const float* __restrict__ us,
    const float* __restrict__ ru,
    float* __restrict__ out,
    int B, int K, long long V)
{
    const int b = blockIdx.x / SLICES;
    const int s = blockIdx.x % SLICES;
    const int t = threadIdx.x;
    const int w = t >> 5;
    const int lane = t & 31;

    __shared__ int sh_red[NW];
    __shared__ int sh_start;
    __shared__ int sh_numacc;
    __shared__ int sh_allacc;
    __shared__ int sh_dtok[32];
    __shared__ int sh_last;

    // ---- starts[b] = sum ndraft[0..b-1]; each thread covers t and t+NT ----
    {
        int v = 0;
        if (t < b) v += ndraft[t];
        if (t + NT < b) v += ndraft[t + NT];
        #pragma unroll
        for (int off = 16; off; off >>= 1)
            v += __shfl_down_sync(0xffffffffu, v, off);
        if (lane == 0) sh_red[w] = v;
        __syncthreads();
        if (t == 0) {
            int sum = 0;
            #pragma unroll
            for (int i = 0; i < NW; i++) sum += sh_red[i];
            sh_start = sum;
        }
        __syncthreads();
    }
    const int start = sh_start;
    const int nb = ndraft[b];

    // ---- accept phase (warp 0; redundant per slice -> L2 hits) ----
    if (t < 32) {
        int k = lane;
        int acc = 0;
        if (k < nb) {
            int idx = start + k;
            int tok = dtoks[idx];
            float pd = fmaxf(dp[(size_t)idx * V + tok], 1e-10f);
            float pt = tp[(size_t)idx * V + tok];
            float ap = fminf(1.0f, pt / pd);
            acc = (us[idx] < ap) ? 1 : 0;
            sh_dtok[k] = tok;
        }
        unsigned m = __ballot_sync(0xffffffffu, (k >= nb) || !acc);
        int numacc = __ffs(m) - 1;
        if (lane == 0) {
            sh_numacc = numacc;
            sh_allacc = (numacc == nb) ? 1 : 0;
        }
    }
    __syncthreads();
    const int numacc = sh_numacc;
    const bool allacc = (sh_allacc != 0);

    // ---- light outputs (slice 0 only) ----
    if (s == 0) {
        if (t <= K) {
            bool is_final = (t == numacc);
            float v;
            if (t < numacc)      v = (float)sh_dtok[t];
            else if (is_final)   v = (float)bonus[b];   // valid only if allacc
            else                 v = -1.0f;
            if (!(is_final && !allacc))
                out[b * (K + 1) + t] = v;
        }
        if (t == 0) {
            int base = B * (K + 1);
            out[base + b]         = (float)(numacc + 1);
            out[base + B + b]     = (float)numacc;
            out[base + 2 * B + b] = allacc ? 0.0f : 1.0f;
            out[base + 3 * B + b] = allacc ? 1.0f : 0.0f;
        }
    }
    if (allacc) return;   // counter untouched: stays 0 for next replay

    // ---- streaming setup: 16B-aligned virtual origin ----
    const int row = start + numacc;
    const long long rowoff = (long long)row * V;
    const int roff = (int)(rowoff & 3);             // elems past 16B boundary
    const float* __restrict__ tA = tp + (rowoff - roff);   // 16B aligned
    const float* __restrict__ dA = dp + (rowoff - roff);
    const long long VL = V + roff;                  // virtual length
    const int nchunks = (int)((VL + CHUNK - 1) / CHUNK);
    const int cps = (nchunks + SLICES - 1) / SLICES;
    const int c0 = s * cps;
    const int c1 = min(c0 + cps, nchunks);

    for (int c = c0 + w; c < c1; c += NW) {
        float sa = 0.f, st = 0.f;
        if (c == 0 || c == nchunks - 1) {
            // scalar masked path (lead phantoms / row tail)
            long long vb = (long long)c * CHUNK + lane * 16;
            #pragma unroll
            for (int l = 0; l < 16; l++) {
                long long vj = vb + l;
                if (vj >= roff && vj < VL) {
                    float tv = tA[vj];       // default cache: keep in L2 for replays
                    float dv = dA[vj];
                    st += tv;
                    sa += fmaxf(tv - dv, 0.f);
                }
            }
        } else {
            // vector path: 8 independent LDG.128, lane-contiguous layout
            const float4* __restrict__ t4 = (const float4*)tA + (long long)c * (CHUNK / 4);
            const float4* __restrict__ d4 = (const float4*)dA + (long long)c * (CHUNK / 4);
            float4 a0 = t4[0 * 32 + lane];
            float4 a1 = t4[1 * 32 + lane];
            float4 a2 = t4[2 * 32 + lane];
            float4 a3 = t4[3 * 32 + lane];
            float4 b0 = d4[0 * 32 + lane];
            float4 b1 = d4[1 * 32 + lane];
            float4 b2 = d4[2 * 32 + lane];
            float4 b3 = d4[3 * 32 + lane];
            st = ((a0.x + a0.y) + (a0.z + a0.w)) + ((a1.x + a1.y) + (a1.z + a1.w))
               + ((a2.x + a2.y) + (a2.z + a2.w)) + ((a3.x + a3.y) + (a3.z + a3.w));
            sa = ((fmaxf(a0.x - b0.x, 0.f) + fmaxf(a0.y - b0.y, 0.f))
               +  (fmaxf(a0.z - b0.z, 0.f) + fmaxf(a0.w - b0.w, 0.f)))
               + ((fmaxf(a1.x - b1.x, 0.f) + fmaxf(a1.y - b1.y, 0.f))
               +  (fmaxf(a1.z - b1.z, 0.f) + fmaxf(a1.w - b1.w, 0.f)))
               + ((fmaxf(a2.x - b2.x, 0.f) + fmaxf(a2.y - b2.y, 0.f))
               +  (fmaxf(a2.z - b2.z, 0.f) + fmaxf(a2.w - b2.w, 0.f)))
               + ((fmaxf(a3.x - b3.x, 0.f) + fmaxf(a3.y - b3.y, 0.f))
               +  (fmaxf(a3.z - b3.z, 0.f) + fmaxf(a3.w - b3.w, 0.f)));
        }
        #pragma unroll
        for (int off = 16; off; off >>= 1) {
            sa += __shfl_down_sync(0xffffffffu, sa, off);
            st += __shfl_down_sync(0xffffffffu, st, off);
        }
        if (lane == 0) {
            g_chunkA[b * MAXC + c] = sa;
            g_chunkT[b * MAXC + c] = st;
        }
    }

    // ---- last-block-does-selection handshake ----
    __threadfence();
    __syncthreads();
    if (t == 0) {
        int prev = atomicAdd(&g_count[b], 1);
        int last = (prev == SLICES - 1);
        if (last) atomicExch(&g_count[b], 0);   // replay-safe reset
        sh_last = last;
    }
    __syncthreads();
    if (!sh_last) return;
    __threadfence();

    // ---- selection: monotone scan over chunk sums, then in-chunk refine ----
    __shared__ float sA[MAXC];
    __shared__ float sT[MAXC];
    __shared__ float sh_thr, sh_coff;
    __shared__ int   sh_cstar, sh_modeT;

    for (int i = t; i < nchunks; i += NT) {
        sA[i] = g_chunkA[b * MAXC + i];
        sT[i] = g_chunkT[b * MAXC + i];
    }
    __syncthreads();

    if (t == 0) {
        float sTot = 0.f;
        for (int c = 0; c < nchunks; c++) sTot += sA[c];
        int modeT = !(sTot > 1e-10f);
        float u = ru[b];
        float thr = modeT ? u : u * sTot;
        const float* cs = modeT ? sT : sA;
        float pref = 0.f, coff = 0.f;
        int cstar = nchunks;
        for (int c = 0; c < nchunks; c++) {
            float np = pref + cs[c];
            if (np >= thr) { cstar = c; coff = pref; break; }
            pref = np;
        }
        sh_thr = thr; sh_coff = coff; sh_cstar = cstar; sh_modeT = modeT;
    }
    __syncthreads();

    if (t < 32) {
        int cstar = sh_cstar;
        int recovered;
        if (cstar >= nchunks) {
            recovered = (int)V - 1;
        } else {
            float thr = sh_thr;
            float off = sh_coff;
            bool modeT = (sh_modeT != 0);
            long long vbase = (long long)cstar * CHUNK;
            float vals[16];
            float lsum = 0.f;
            #pragma unroll
            for (int l = 0; l < 16; l++) {
                long long vj = vbase + lane * 16 + l;
                float a = 0.f;
                if (vj >= roff && vj < VL) {
                    float tv = tA[vj];
                    a = modeT ? tv : fmaxf(tv - dA[vj], 0.f);
                }
                vals[l] = a;
                lsum += a;
            }
            float incv = lsum;
            #pragma unroll
            for (int d = 1; d < 32; d <<= 1) {
                float y = __shfl_up_sync(0xffffffffu, incv, d);
                if (lane >= d) incv += y;
            }
            float p = off + (incv - lsum);
            int cnt = 0;
            #pragma unroll
            for (int l = 0; l < 16; l++) {
                p += vals[l];
                long long vj = vbase + lane * 16 + l;
                if (p < thr && vj >= roff && vj < VL) cnt++;
            }
            #pragma unroll
            for (int o = 16; o; o >>= 1)
                cnt += __shfl_down_sync(0xffffffffu, cnt, o);
            int before = (int)vbase - roff;
            if (before < 0) before = 0;
            recovered = before + cnt;
            if (recovered > (int)V - 1) recovered = (int)V - 1;
        }
        if (lane == 0)
            out[b * (K + 1) + numacc] = (float)recovered;
    }
}

extern "C" void kernel_launch(void* const* d_in, const int* in_sizes, int n_in,
                              void* d_out, int out_size)
{
    const int*   dtoks  = (const int*)  d_in[0];
    const int*   ndraft = (const int*)  d_in[1];
    const float* dp     = (const float*)d_in[2];
    const float* tp     = (const float*)d_in[3];
    const int*   bonus  = (const int*)  d_in[4];
    const float* us     = (const float*)d_in[5];
    const float* ru     = (const float*)d_in[6];

    int T = in_sizes[0];
    int B = in_sizes[1];
    long long V = (long long)in_sizes[2] / T;
    int K = out_size / B - 5;   // out layout: B*(K+1) + 4*B

    fused_kernel<<<B * SLICES, NT>>>(dtoks, ndraft, dp, tp, bonus, us, ru,
                                     (float*)d_out, B, K, V);
}